// round 6
// baseline (speedup 1.0000x reference)
#include <cuda_runtime.h>
#include <math.h>

#define Bc  4
#define Nc  2048
#define Cc  256
#define Hc  8
#define Dhc 32

__device__ float g_q[Bc * Nc * Cc];
__device__ float g_k[Bc * Nc * Cc];
__device__ float g_v[Bc * Nc * Cc];
__device__ float g_x[Bc * Nc * Cc];
__device__ float g_maskT[(size_t)Bc * Nc * Nc];

__device__ __forceinline__ float to_tf32(float x) {
    asm("cvt.rna.tf32.f32 %0, %1;" : "=f"(x) : "f"(x));
    return x;
}
__device__ __forceinline__ float ex2f(float x) {
    float y;
    asm("ex2.approx.ftz.f32 %0, %1;" : "=f"(y) : "f"(x));
    return y;
}
__device__ __forceinline__ void mma8(float d[4], float a0, float a1, float a2, float a3,
                                     float b0, float b1) {
    asm volatile(
        "mma.sync.aligned.m16n8k8.row.col.f32.tf32.tf32.f32 "
        "{%0,%1,%2,%3}, {%4,%5,%6,%7}, {%8,%9}, {%0,%1,%2,%3};"
        : "+f"(d[0]), "+f"(d[1]), "+f"(d[2]), "+f"(d[3])
        : "r"(__float_as_uint(a0)), "r"(__float_as_uint(a1)),
          "r"(__float_as_uint(a2)), "r"(__float_as_uint(a3)),
          "r"(__float_as_uint(b0)), "r"(__float_as_uint(b1)));
}
__device__ __forceinline__ float* bufsel(int s) {
    switch (s) {
        case 0: return g_q;
        case 1: return g_k;
        case 2: return g_v;
        default: return g_x;
    }
}

// maskT[b][q][k] = mask[b][k][q] / max_k mask[b][k][q]
__global__ __launch_bounds__(256) void mask_prep_kernel(const float* __restrict__ mask) {
    const int qt = blockIdx.x, b = blockIdx.y;
    const int q0 = qt * 64, t = threadIdx.x;
    __shared__ float red[4][64];
    __shared__ float cinv[64];
    __shared__ float ts[64][65];
    const int qj = t & 63, kr = t >> 6;
    const float* mb = mask + (size_t)b * Nc * Nc;

    float lmax = 0.f;
    for (int k = kr; k < Nc; k += 4)
        lmax = fmaxf(lmax, mb[(size_t)k * Nc + q0 + qj]);
    red[kr][qj] = lmax;
    __syncthreads();
    if (t < 64)
        cinv[t] = 1.0f / fmaxf(fmaxf(red[0][t], red[1][t]), fmaxf(red[2][t], red[3][t]));
    __syncthreads();

    float* mtb = g_maskT + (size_t)b * Nc * Nc;
    for (int k0 = 0; k0 < Nc; k0 += 64) {
        #pragma unroll 4
        for (int ii = 0; ii < 16; ii++) {
            int i = kr + 4 * ii;
            ts[i][qj] = mb[(size_t)(k0 + i) * Nc + q0 + qj];
        }
        __syncthreads();
        #pragma unroll 4
        for (int jj = 0; jj < 16; jj++) {
            int j = kr + 4 * jj;
            mtb[(size_t)(q0 + j) * Nc + k0 + qj] = ts[qj][j] * cinv[j];
        }
        __syncthreads();
    }
}

// Out[m][n] = (sum_k A[m][k]*W[n][k] + bias[n])*scale + resid[m][n]
__global__ __launch_bounds__(128) void gemm_kernel(
    const float* __restrict__ Aext, int asel,
    const float* __restrict__ W, const float* __restrict__ bias,
    const float* __restrict__ resid,
    float* __restrict__ Oext, int osel, float scale)
{
    const int Kd = Cc, Nd = Cc;
    const float* A = (asel >= 0) ? bufsel(asel) : Aext;
    float* Out = (osel >= 0) ? bufsel(osel) : Oext;

    const int m0 = blockIdx.x * 64, n0 = blockIdx.y * 64;
    __shared__ float As[64][36];
    __shared__ float Ws[64][36];
    const int tid = threadIdx.x, warp = tid >> 5, lane = tid & 31;
    const int wq = warp >> 1, wn = warp & 1, lg = lane >> 2, lr = lane & 3;
    const int r = tid >> 1, cs = (tid & 1) * 16;

    float acc[2][4][4];
    #pragma unroll
    for (int a = 0; a < 2; a++)
        #pragma unroll
        for (int bb = 0; bb < 4; bb++)
            #pragma unroll
            for (int c = 0; c < 4; c++) acc[a][bb][c] = 0.f;

    for (int k0 = 0; k0 < Kd; k0 += 32) {
        __syncthreads();
        const float4* pa = (const float4*)(A + (size_t)(m0 + r) * Kd + k0 + cs);
        const float4* pw = (const float4*)(W + (size_t)(n0 + r) * Kd + k0 + cs);
        #pragma unroll
        for (int i = 0; i < 4; i++) {
            float4 v = pa[i];
            v.x = to_tf32(v.x); v.y = to_tf32(v.y); v.z = to_tf32(v.z); v.w = to_tf32(v.w);
            *(float4*)&As[r][cs + 4 * i] = v;
            float4 w = pw[i];
            w.x = to_tf32(w.x); w.y = to_tf32(w.y); w.z = to_tf32(w.z); w.w = to_tf32(w.w);
            *(float4*)&Ws[r][cs + 4 * i] = w;
        }
        __syncthreads();
        #pragma unroll
        for (int kc = 0; kc < 4; kc++) {
            float a[2][4];
            #pragma unroll
            for (int mt = 0; mt < 2; mt++) {
                int row = wq * 32 + mt * 16 + lg;
                a[mt][0] = As[row][kc * 8 + lr];
                a[mt][1] = As[row + 8][kc * 8 + lr];
                a[mt][2] = As[row][kc * 8 + lr + 4];
                a[mt][3] = As[row + 8][kc * 8 + lr + 4];
            }
            #pragma unroll
            for (int nt = 0; nt < 4; nt++) {
                int nrow = wn * 32 + nt * 8 + lg;
                float b0 = Ws[nrow][kc * 8 + lr];
                float b1 = Ws[nrow][kc * 8 + lr + 4];
                mma8(acc[0][nt], a[0][0], a[0][1], a[0][2], a[0][3], b0, b1);
                mma8(acc[1][nt], a[1][0], a[1][1], a[1][2], a[1][3], b0, b1);
            }
        }
    }
    #pragma unroll
    for (int mt = 0; mt < 2; mt++)
        #pragma unroll
        for (int nt = 0; nt < 4; nt++)
            #pragma unroll
            for (int hi = 0; hi < 2; hi++) {
                int row = m0 + wq * 32 + mt * 16 + lg + hi * 8;
                int col = n0 + wn * 32 + nt * 8 + 2 * lr;
                float2 o;
                o.x = (acc[mt][nt][hi * 2] + bias[col]) * scale;
                o.y = (acc[mt][nt][hi * 2 + 1] + bias[col + 1]) * scale;
                if (resid) {
                    o.x += resid[(size_t)row * Nd + col];
                    o.y += resid[(size_t)row * Nd + col + 1];
                }
                *(float2*)(Out + (size_t)row * Nd + col) = o;
            }
}

// per (h, q-tile, b): pass1 rowsums of exp2(S); pass2 recompute S, emit attn_vis, mask, PV
__global__ __launch_bounds__(128) void attn_kernel(float* __restrict__ attn_vis) {
    const int h = blockIdx.x, qt = blockIdx.y, b = blockIdx.z;
    const int q0 = qt * 64;
    const int tid = threadIdx.x, warp = tid >> 5, lane = tid & 31;
    const int wq = warp >> 1, wk = warp & 1, lg = lane >> 2, lr = lane & 3;

    __shared__ float Qs[64][36];
    __shared__ float Ks[64][36];
    __shared__ float Vs[64][40];
    __shared__ float Ps[64][68];
    __shared__ float rsum[64];
    __shared__ float rinv_s[64];

    const int r = tid >> 1, cs = (tid & 1) * 16;
    {
        const float4* src = (const float4*)(g_q + (size_t)(b * Nc + q0 + r) * Cc + h * Dhc + cs);
        #pragma unroll
        for (int i = 0; i < 4; i++) {
            float4 v = src[i];
            v.x = to_tf32(v.x); v.y = to_tf32(v.y); v.z = to_tf32(v.z); v.w = to_tf32(v.w);
            *(float4*)&Qs[r][cs + 4 * i] = v;
        }
    }
    if (tid < 64) rsum[tid] = 0.f;

    const float* Kb = g_k + (size_t)b * Nc * Cc + h * Dhc;
    const float* Vb = g_v + (size_t)b * Nc * Cc + h * Dhc;

    float psum[4] = {0.f, 0.f, 0.f, 0.f};

    // ---- pass 1 ----
    for (int kt = 0; kt < Nc / 64; kt++) {
        __syncthreads();
        {
            const float4* sk = (const float4*)(Kb + (size_t)(kt * 64 + r) * Cc + cs);
            #pragma unroll
            for (int i = 0; i < 4; i++) {
                float4 v = sk[i];
                v.x = to_tf32(v.x); v.y = to_tf32(v.y); v.z = to_tf32(v.z); v.w = to_tf32(v.w);
                *(float4*)&Ks[r][cs + 4 * i] = v;
            }
        }
        __syncthreads();
        float acc[2][4][4];
        #pragma unroll
        for (int a = 0; a < 2; a++)
            #pragma unroll
            for (int bb = 0; bb < 4; bb++)
                #pragma unroll
                for (int c = 0; c < 4; c++) acc[a][bb][c] = 0.f;
        #pragma unroll
        for (int kc = 0; kc < 4; kc++) {
            float a[2][4];
            #pragma unroll
            for (int mt = 0; mt < 2; mt++) {
                int row = wq * 32 + mt * 16 + lg;
                a[mt][0] = Qs[row][kc * 8 + lr];
                a[mt][1] = Qs[row + 8][kc * 8 + lr];
                a[mt][2] = Qs[row][kc * 8 + lr + 4];
                a[mt][3] = Qs[row + 8][kc * 8 + lr + 4];
            }
            #pragma unroll
            for (int nt = 0; nt < 4; nt++) {
                int nrow = wk * 32 + nt * 8 + lg;
                float b0 = Ks[nrow][kc * 8 + lr];
                float b1 = Ks[nrow][kc * 8 + lr + 4];
                mma8(acc[0][nt], a[0][0], a[0][1], a[0][2], a[0][3], b0, b1);
                mma8(acc[1][nt], a[1][0], a[1][1], a[1][2], a[1][3], b0, b1);
            }
        }
        #pragma unroll
        for (int mt = 0; mt < 2; mt++)
            #pragma unroll
            for (int nt = 0; nt < 4; nt++)
                #pragma unroll
                for (int i2 = 0; i2 < 4; i2++)
                    psum[mt * 2 + (i2 >> 1)] += ex2f(acc[mt][nt][i2]);
    }
    __syncthreads();
    #pragma unroll
    for (int j = 0; j < 4; j++) {
        float v = psum[j];
        v += __shfl_xor_sync(0xffffffffu, v, 1);
        v += __shfl_xor_sync(0xffffffffu, v, 2);
        if (lr == 0) atomicAdd(&rsum[wq * 32 + (j >> 1) * 16 + lg + (j & 1) * 8], v);
    }
    __syncthreads();
    if (tid < 64) rinv_s[tid] = 1.0f / rsum[tid];

    float xacc[4][4];
    #pragma unroll
    for (int a = 0; a < 4; a++)
        #pragma unroll
        for (int c = 0; c < 4; c++) xacc[a][c] = 0.f;

    const float* mtb = g_maskT + (size_t)b * Nc * Nc;
    float* av = attn_vis + (size_t)(b * Hc + h) * Nc * Nc;

    // ---- pass 2 ----
    for (int kt = 0; kt < Nc / 64; kt++) {
        __syncthreads();
        {
            const float4* sk = (const float4*)(Kb + (size_t)(kt * 64 + r) * Cc + cs);
            const float4* sv = (const float4*)(Vb + (size_t)(kt * 64 + r) * Cc + cs);
            #pragma unroll
            for (int i = 0; i < 4; i++) {
                float4 v = sk[i];
                v.x = to_tf32(v.x); v.y = to_tf32(v.y); v.z = to_tf32(v.z); v.w = to_tf32(v.w);
                *(float4*)&Ks[r][cs + 4 * i] = v;
                float4 w = sv[i];
                w.x = to_tf32(w.x); w.y = to_tf32(w.y); w.z = to_tf32(w.z); w.w = to_tf32(w.w);
                *(float4*)&Vs[r][cs + 4 * i] = w;
            }
        }
        __syncthreads();
        float acc[2][4][4];
        #pragma unroll
        for (int a = 0; a < 2; a++)
            #pragma unroll
            for (int bb = 0; bb < 4; bb++)
                #pragma unroll
                for (int c = 0; c < 4; c++) acc[a][bb][c] = 0.f;
        #pragma unroll
        for (int kc = 0; kc < 4; kc++) {
            float a[2][4];
            #pragma unroll
            for (int mt = 0; mt < 2; mt++) {
                int row = wq * 32 + mt * 16 + lg;
                a[mt][0] = Qs[row][kc * 8 + lr];
                a[mt][1] = Qs[row + 8][kc * 8 + lr];
                a[mt][2] = Qs[row][kc * 8 + lr + 4];
                a[mt][3] = Qs[row + 8][kc * 8 + lr + 4];
            }
            #pragma unroll
            for (int nt = 0; nt < 4; nt++) {
                int nrow = wk * 32 + nt * 8 + lg;
                float b0 = Ks[nrow][kc * 8 + lr];
                float b1 = Ks[nrow][kc * 8 + lr + 4];
                mma8(acc[0][nt], a[0][0], a[0][1], a[0][2], a[0][3], b0, b1);
                mma8(acc[1][nt], a[1][0], a[1][1], a[1][2], a[1][3], b0, b1);
            }
        }
        #pragma unroll
        for (int mt = 0; mt < 2; mt++)
            #pragma unroll
            for (int nt = 0; nt < 4; nt++)
                #pragma unroll
                for (int hi = 0; hi < 2; hi++) {
                    int row = wq * 32 + mt * 16 + lg + hi * 8;
                    int col = wk * 32 + nt * 8 + 2 * lr;
                    int kg = kt * 64 + col;
                    float rv = rinv_s[row];
                    float p0 = ex2f(acc[mt][nt][hi * 2]) * rv;
                    float p1 = ex2f(acc[mt][nt][hi * 2 + 1]) * rv;
                    *(float2*)(av + (size_t)(q0 + row) * Nc + kg) = make_float2(p0, p1);
                    float2 m2 = *(const float2*)(mtb + (size_t)(q0 + row) * Nc + kg);
                    *(float2*)&Ps[row][col] =
                        make_float2(to_tf32(p0 * m2.x), to_tf32(p1 * m2.y));
                }
        __syncthreads();
        #pragma unroll
        for (int kc = 0; kc < 8; kc++) {
            int prow = warp * 16 + lg;
            float a0 = Ps[prow][kc * 8 + lr];
            float a1 = Ps[prow + 8][kc * 8 + lr];
            float a2 = Ps[prow][kc * 8 + lr + 4];
            float a3 = Ps[prow + 8][kc * 8 + lr + 4];
            #pragma unroll
            for (int nt = 0; nt < 4; nt++) {
                float b0 = Vs[kc * 8 + lr][nt * 8 + lg];
                float b1 = Vs[kc * 8 + lr + 4][nt * 8 + lg];
                mma8(xacc[nt], a0, a1, a2, a3, b0, b1);
            }
        }
    }
    #pragma unroll
    for (int nt = 0; nt < 4; nt++)
        #pragma unroll
        for (int hi = 0; hi < 2; hi++) {
            int row = q0 + warp * 16 + lg + hi * 8;
            int col = h * Dhc + nt * 8 + 2 * lr;
            *(float2*)(g_x + (size_t)(b * Nc + row) * Cc + col) =
                make_float2(xacc[nt][hi * 2], xacc[nt][hi * 2 + 1]);
        }
}

extern "C" void kernel_launch(void* const* d_in, const int* in_sizes, int n_in,
                              void* d_out, int out_size) {
    const float* query = (const float*)d_in[0];
    const float* amask = (const float*)d_in[1];
    const float* Wq = (const float*)d_in[2];
    const float* bq = (const float*)d_in[3];
    const float* Wk = (const float*)d_in[4];
    const float* bk = (const float*)d_in[5];
    const float* Wv = (const float*)d_in[6];
    const float* bv = (const float*)d_in[7];
    const float* Wo = (const float*)d_in[8];
    const float* bo = (const float*)d_in[9];

    float* out = (float*)d_out;
    float* attn_vis = out + (size_t)Bc * Nc * Cc;

    // SCALE * log2(e) folded into Q so exp(S*SCALE) == exp2(Sq)
    const float QS = 0.17677669529663687f * 1.4426950408889634f;

    dim3 gg(Bc * Nc / 64, Cc / 64);
    mask_prep_kernel<<<dim3(Nc / 64, Bc), 256>>>(amask);
    gemm_kernel<<<gg, 128>>>(query, -1, Wq, bq, nullptr, nullptr, 0, QS);
    gemm_kernel<<<gg, 128>>>(query, -1, Wk, bk, nullptr, nullptr, 1, 1.0f);
    gemm_kernel<<<gg, 128>>>(query, -1, Wv, bv, nullptr, nullptr, 2, 1.0f);
    attn_kernel<<<dim3(Hc, Nc / 64, Bc), 128>>>(attn_vis);
    gemm_kernel<<<gg, 128>>>(nullptr, 3, Wo, bo, query, out, -1, 1.0f);
}